// round 14
// baseline (speedup 1.0000x reference)
#include <cuda_runtime.h>
#include <cuda_fp16.h>
#include <stdint.h>
#include <math.h>

// ---------------- problem dims ----------------------------------------------
#define NB   4
#define NL   2048
#define ND   1024
#define NH   4096
#define NV   32000
#define NEXP 16
#define NTOK (NB*NL)     // 8192
#define KCAT (2*NH)      // 8192

#define ASCALE 1024.0f
#define INVS   (1.0f/1024.0f)

// ---------------- persistent fp16 operand storage ----------------------------
// token-side operands carry x1024 scale, single fp16 digit
__device__ __half g_Xh[NTOK * ND];
__device__ __half g_Hh[(size_t)NTOK * KCAT];
__device__ __half g_Oh[NTOK * ND];
// weight-side operands (B): single fp16, unscaled
__device__ __half g_w1f[(size_t)2 * NH * ND];
__device__ __half g_w2f[(size_t)ND * KCAT];
__device__ __half g_whf[(size_t)NV * ND];
__device__ float g_pool_part[64 * ND];
__device__ float g_pool[ND];
__device__ int   g_eidx[2];
__device__ float g_ewt[2];

// ---------------- helpers -----------------------------------------------------
__device__ __forceinline__ float gelu_tanh(float x) {
    const float u = 0.7978845608028654f * (x + 0.044715f * x * x * x);
    return 0.5f * x * (1.0f + tanhf(u));
}
__device__ __forceinline__ uint32_t pkh(__half a, __half b) {
    return (uint32_t)__half_as_ushort(a) |
           ((uint32_t)__half_as_ushort(b) << 16);
}
__device__ __forceinline__ uint32_t s2u(const void* p) {
    uint32_t a;
    asm("{ .reg .u64 t; cvta.to.shared.u64 t, %1; cvt.u32.u64 %0, t; }"
        : "=r"(a) : "l"(p));
    return a;
}

__device__ __forceinline__ void mma_f16(float* d, const uint32_t* a,
                                        const uint32_t* b) {
    asm volatile(
        "mma.sync.aligned.m16n8k16.row.col.f32.f16.f16.f32 "
        "{%0,%1,%2,%3}, {%4,%5,%6,%7}, {%8,%9}, {%0,%1,%2,%3};"
        : "+f"(d[0]), "+f"(d[1]), "+f"(d[2]), "+f"(d[3])
        : "r"(a[0]), "r"(a[1]), "r"(a[2]), "r"(a[3]),
          "r"(b[0]), "r"(b[1]));
}

#define LDSM4(r0, r1, r2, r3, addr) \
    asm volatile("ldmatrix.sync.aligned.m8n8.x4.shared.b16 {%0,%1,%2,%3}, [%4];" \
        : "=r"(r0), "=r"(r1), "=r"(r2), "=r"(r3) : "r"(addr))

#define CPASYNC16(dst, src) \
    asm volatile("cp.async.cg.shared.global [%0], [%1], 16;" \
        :: "r"(dst), "l"(src) : "memory")
#define CPCOMMIT() asm volatile("cp.async.commit_group;" ::: "memory")
#define CPWAIT2()  asm volatile("cp.async.wait_group 2;"  ::: "memory")

// chunk swizzle: 16B chunks, ci ^ bit3->bit0 (keeps ldmatrix 8-row phases conflict-free)
#define SWZ16(ci) ((uint32_t)(((ci) ^ (((ci) >> 3) & 1)) * 16))

// ---------------- embed / pool / router --------------------------------------
__global__ void gather_half_kernel(const int* __restrict__ ids,
                                   const float* __restrict__ emb)
{
    const int t = blockIdx.x;
    const int id = ids[t];
    const int c = threadIdx.x * 4;
    float4 v = *(const float4*)(emb + (size_t)id * ND + c);
    *(uint2*)(g_Xh + (size_t)t * ND + c) =
        make_uint2(pkh(__float2half_rn(v.x * ASCALE), __float2half_rn(v.y * ASCALE)),
                   pkh(__float2half_rn(v.z * ASCALE), __float2half_rn(v.w * ASCALE)));
}

__global__ void pool_partial_kernel(const int* __restrict__ ids,
                                    const float* __restrict__ emb)
{
    __shared__ int sid[128];
    const int t0 = blockIdx.x * 128;
    if (threadIdx.x < 128) sid[threadIdx.x] = ids[t0 + threadIdx.x];
    __syncthreads();
    const int c = threadIdx.x * 4;
    float4 s = make_float4(0.f, 0.f, 0.f, 0.f);
    for (int t = 0; t < 128; ++t) {
        const float4 v = *(const float4*)(emb + (size_t)sid[t] * ND + c);
        s.x += v.x; s.y += v.y; s.z += v.z; s.w += v.w;
    }
    *(float4*)(g_pool_part + blockIdx.x * ND + c) = s;
}

__global__ void pool_final_kernel()
{
    const int c = threadIdx.x * 4;
    float4 s = make_float4(0.f, 0.f, 0.f, 0.f);
    for (int b = 0; b < 64; ++b) {
        const float4 v = *(const float4*)(g_pool_part + b * ND + c);
        s.x += v.x; s.y += v.y; s.z += v.z; s.w += v.w;
    }
    const float inv = 1.0f / (float)NTOK;
    s.x *= inv; s.y *= inv; s.z *= inv; s.w *= inv;
    *(float4*)(g_pool + c) = s;
}

__global__ void router_kernel(const float* __restrict__ w_router)
{
    __shared__ float slog[NEXP];
    const int warp = threadIdx.x >> 5;
    const int lane = threadIdx.x & 31;
    float s = 0.f;
    for (int d = lane; d < ND; d += 32)
        s += g_pool[d] * w_router[d * NEXP + warp];
    #pragma unroll
    for (int o = 16; o > 0; o >>= 1) s += __shfl_down_sync(0xffffffffu, s, o);
    if (lane == 0) slog[warp] = s;
    __syncthreads();
    if (threadIdx.x == 0) {
        float v0 = -1e30f, v1 = -1e30f; int i0 = 0, i1 = 0;
        for (int n = 0; n < NEXP; ++n) {
            const float l = slog[n];
            if (l > v0) { v1 = v0; i1 = i0; v0 = l; i0 = n; }
            else if (l > v1) { v1 = l; i1 = n; }
        }
        const float e1  = expf(v1 - v0);
        const float den = 1.0f + e1;
        g_eidx[0] = i0; g_eidx[1] = i1;
        g_ewt[0] = 1.0f / den; g_ewt[1] = e1 / den;
    }
}

// ---------------- weight transpose (fp16 single) -------------------------------
__global__ void transpose_half_kernel(const float* __restrict__ src,
                                      int K, int N, long src_z, int mode)
{
    __shared__ float tile[32][33];
    const int e = blockIdx.z;
    __half* dh; long dst_z; int ld; int use_e;
    if (mode == 0)      { dh = g_w1f; dst_z = (long)NH * ND; ld = ND;   use_e = 1; }
    else if (mode == 1) { dh = g_w2f; dst_z = NH;            ld = KCAT; use_e = 1; }
    else                { dh = g_whf; dst_z = 0;             ld = ND;   use_e = 0; }

    const int sel = use_e ? g_eidx[e] : e;
    const float* in = src + (size_t)sel * src_z;
    dh += (size_t)e * dst_z;

    const int n0 = blockIdx.x * 32, k0 = blockIdx.y * 32;
    const int tx = threadIdx.x, ty = threadIdx.y;   // (32, 8)
    #pragma unroll
    for (int j = 0; j < 32; j += 8)
        tile[ty + j][tx] = in[(size_t)(k0 + ty + j) * N + n0 + tx];
    __syncthreads();
    #pragma unroll
    for (int j = 0; j < 32; j += 8)
        dh[(size_t)(n0 + ty + j) * ld + k0 + tx] =
            __float2half_rn(tile[tx][ty + j]);
}

// ---------------- fp16 single-product mma GEMM, BK=32 dual sub-stage -----------
// C = A @ B^T, both operands single fp16 (A carries x1024 scale).
// 128-thread CTA, 4 warps 2x2, warp tile 64x64, 4-stage cp.async, 2 CTAs/SM.
// Each 16KB stage = two 8KB sub-stages (k and k+16) in the verified BK=16 layout:
//   A0 @ 0, A1 @ 4096, B0 @ 8192, B1 @ 12288
#define BM 128
#define BN 128
#define BK 32
#define NSTAGE 4
#define SUB    4096
#define OFF_B  8192
#define STAGE  16384
#define SMEM_BYTES (NSTAGE * STAGE)   // 65536 per CTA; 2 CTAs = 128KB/SM

// MODE 0: H = gelu(X @ w1t[e]^T)*wt[e] -> Hh   (grid.z = expert)
// MODE 1: O = H @ w2t^T -> Oh
// MODE 2: LOGITS = O @ wht^T -> fp32 out
template<int MODE>
__global__ void __launch_bounds__(128, 2)
mma_gemm_kernel(float* __restrict__ Cext)
{
    constexpr int K   = (MODE == 1) ? KCAT : ND;
    constexpr int NT  = K / BK;
    constexpr int LDC = (MODE == 0) ? KCAT : ((MODE == 1) ? ND : NV);

    const __half *Ah, *Bh_;
    if (MODE == 0)      { Ah = g_Xh; Bh_ = g_w1f; }
    else if (MODE == 1) { Ah = g_Hh; Bh_ = g_w2f; }
    else                { Ah = g_Oh; Bh_ = g_whf; }

    extern __shared__ __align__(16) uint8_t smraw[];
    const uint32_t smb = s2u(smraw);

    const int tid  = threadIdx.x;
    const int w    = tid >> 5, lane = tid & 31;
    const int g    = lane >> 2, tig = lane & 3;
    const int mb   = (w >> 1) * 64;        // 2 m-warps
    const int nb   = (w & 1) * 64;         // 2 n-warps
    const int bm   = blockIdx.y * BM;
    const int bn   = blockIdx.x * BN;

    float wt = 1.f; int ccol0 = bn;
    if (MODE == 0) {
        const int e = blockIdx.z;
        wt    = g_ewt[e];
        Bh_  += (size_t)e * NH * ND;
        ccol0 = e * NH + bn;
    }

    const __half* Ab_h = Ah + (size_t)bm * K;
    const __half* Bb_h = Bh_ + (size_t)bn * K;

    // fill one 16KB stage: two BK=16 sub-stages at k0 and k0+16
    auto fill = [&](uint32_t sbase, int k0) {
        #pragma unroll
        for (int i = 0; i < 2; ++i) {
            const int ci = i * 128 + tid;
            const int row = ci >> 1, kc = (ci & 1) * 8;
            const size_t go0 = (size_t)row * K + k0 + kc;
            const size_t go1 = go0 + 16;
            const uint32_t so = SWZ16(ci);
            CPASYNC16(sbase + so,               Ab_h + go0);
            CPASYNC16(sbase + SUB + so,         Ab_h + go1);
            CPASYNC16(sbase + OFF_B + so,       Bb_h + go0);
            CPASYNC16(sbase + OFF_B + SUB + so, Bb_h + go1);
        }
    };

    // ldmatrix lane offsets (verified mapping, rounds 5-12; sub-stage relative)
    const int am = lane >> 3;
    const int a_ci0 = (mb + ((am & 1) << 3) + (lane & 7)) * 2 + (am >> 1);
    const uint32_t aoff = SWZ16(a_ci0);
    const int bmm = lane >> 3;
    const int b_ci0 = (nb + ((bmm >> 1) << 3) + (lane & 7)) * 2 + (bmm & 1);
    const uint32_t boff = SWZ16(b_ci0);

    float acc[4][8][4];
    #pragma unroll
    for (int i = 0; i < 4; ++i)
        #pragma unroll
        for (int j = 0; j < 8; ++j)
            #pragma unroll
            for (int q = 0; q < 4; ++q) acc[i][j][q] = 0.f;

    // prologue: stages 0,1,2 in flight
    fill(smb, 0);                  CPCOMMIT();
    fill(smb + STAGE, BK);         CPCOMMIT();
    fill(smb + 2 * STAGE, 2 * BK); CPCOMMIT();

    int rd = 0, wr = 3;
    #pragma unroll 1
    for (int t = 0; t < NT; ++t) {
        CPWAIT2();
        __syncthreads();

        const uint32_t sb = smb + rd * STAGE;
        bool filled = false;

        #pragma unroll
        for (int s = 0; s < 2; ++s) {
            const uint32_t sbA = sb + s * SUB;
            const uint32_t sbB = sb + OFF_B + s * SUB;

            // B fragments for all 8 n-tiles
            uint32_t Bhf[8][2];
            #pragma unroll
            for (int p = 0; p < 4; ++p) {
                uint32_t r0, r1, r2, r3;
                LDSM4(r0, r1, r2, r3, sbB + boff + p * 512);
                Bhf[2*p][0] = r0; Bhf[2*p][1] = r1;
                Bhf[2*p+1][0] = r2; Bhf[2*p+1][1] = r3;
            }

            if (!filled) {
                if (t + 3 < NT) fill(smb + wr * STAGE, (t + 3) * BK);
                CPCOMMIT();
                filled = true;
            }

            #pragma unroll
            for (int mt = 0; mt < 4; ++mt) {
                uint32_t Ahf[4];
                LDSM4(Ahf[0], Ahf[1], Ahf[2], Ahf[3], sbA + aoff + mt * 512);
                #pragma unroll
                for (int nt = 0; nt < 8; ++nt)
                    mma_f16(acc[mt][nt], Ahf, Bhf[nt]);
            }
        }

        rd = (rd + 1) & 3;
        wr = (wr + 1) & 3;
    }

    // ---- epilogue (acc carries x1024 scale from A) ----
    #pragma unroll
    for (int mt = 0; mt < 4; ++mt) {
        const int row0 = bm + mb + mt * 16 + g;
        #pragma unroll
        for (int rr = 0; rr < 2; ++rr) {
            const int row = row0 + rr * 8;
            const size_t base = (size_t)row * LDC + ccol0 + nb + 2 * tig;
            #pragma unroll
            for (int nt = 0; nt < 8; ++nt) {
                float v0 = acc[mt][nt][2 * rr];
                float v1 = acc[mt][nt][2 * rr + 1];
                if (MODE == 0) {   // true value, gelu, re-apply scale
                    v0 = gelu_tanh(v0 * INVS) * wt * ASCALE;
                    v1 = gelu_tanh(v1 * INVS) * wt * ASCALE;
                }
                if (MODE == 2) {
                    *(float2*)(Cext + base + nt * 8) =
                        make_float2(v0 * INVS, v1 * INVS);
                } else {
                    __half* dh = (MODE == 0) ? g_Hh : g_Oh;
                    *(uint32_t*)(dh + base + nt * 8) =
                        pkh(__float2half_rn(v0), __float2half_rn(v1));
                }
            }
        }
    }
}

// ---------------- entry point -------------------------------------------------
extern "C" void kernel_launch(void* const* d_in, const int* in_sizes, int n_in,
                              void* d_out, int out_size)
{
    (void)in_sizes; (void)n_in; (void)out_size;
    const int*   ids = (const int*)  d_in[0];
    const float* emb = (const float*)d_in[1];
    const float* wr  = (const float*)d_in[2];
    const float* w1  = (const float*)d_in[3];
    const float* w2  = (const float*)d_in[4];
    const float* wh  = (const float*)d_in[5];
    float* out = (float*)d_out;

    cudaFuncSetAttribute(mma_gemm_kernel<0>, cudaFuncAttributeMaxDynamicSharedMemorySize, SMEM_BYTES);
    cudaFuncSetAttribute(mma_gemm_kernel<1>, cudaFuncAttributeMaxDynamicSharedMemorySize, SMEM_BYTES);
    cudaFuncSetAttribute(mma_gemm_kernel<2>, cudaFuncAttributeMaxDynamicSharedMemorySize, SMEM_BYTES);

    gather_half_kernel <<<NTOK, 256>>>(ids, emb);
    pool_partial_kernel<<<64,   256>>>(ids, emb);
    pool_final_kernel  <<<1,    256>>>();
    router_kernel      <<<1,    512>>>(wr);

    transpose_half_kernel<<<dim3(NH / 32, ND / 32, 2), dim3(32, 8)>>>(w1, ND, NH, (long)ND * NH, 0);
    transpose_half_kernel<<<dim3(ND / 32, NH / 32, 2), dim3(32, 8)>>>(w2, NH, ND, (long)NH * ND, 1);
    transpose_half_kernel<<<dim3(NV / 32, ND / 32, 1), dim3(32, 8)>>>(wh, ND, NV, 0, 2);

    mma_gemm_kernel<0><<<dim3(NH / BN, NTOK / BM, 2), 128, SMEM_BYTES>>>(nullptr);
    mma_gemm_kernel<1><<<dim3(ND / BN, NTOK / BM, 1), 128, SMEM_BYTES>>>(nullptr);
    mma_gemm_kernel<2><<<dim3(NV / BN, NTOK / BM, 1), 128, SMEM_BYTES>>>(out);
}

// round 15
// speedup vs baseline: 1.2351x; 1.2351x over previous
#include <cuda_runtime.h>
#include <cuda_fp16.h>
#include <stdint.h>
#include <math.h>

// ---------------- problem dims ----------------------------------------------
#define NB   4
#define NL   2048
#define ND   1024
#define NH   4096
#define NV   32000
#define NEXP 16
#define NTOK (NB*NL)     // 8192
#define KCAT (2*NH)      // 8192

#define ASCALE 1024.0f
#define INVS   (1.0f/1024.0f)

// ---------------- persistent fp16 operand storage ----------------------------
// token-side operands carry x1024 scale, single fp16 digit
__device__ __half g_Xh[NTOK * ND];
__device__ __half g_Hh[(size_t)NTOK * KCAT];
__device__ __half g_Oh[NTOK * ND];
// weight-side operands (B): single fp16, unscaled
__device__ __half g_w1f[(size_t)2 * NH * ND];
__device__ __half g_w2f[(size_t)ND * KCAT];
__device__ __half g_whf[(size_t)NV * ND];
__device__ float g_pool_part[64 * ND];
__device__ float g_pool[ND];
__device__ int   g_eidx[2];
__device__ float g_ewt[2];

// ---------------- helpers -----------------------------------------------------
// fast gelu: single-instruction tanh.approx.f32 (sm_75+), abs err ~2^-11 —
// negligible next to the fp16 quantization of H that immediately follows.
__device__ __forceinline__ float gelu_fast(float x) {
    const float u = 0.7978845608028654f * (x + 0.044715f * x * x * x);
    float t;
    asm("tanh.approx.f32 %0, %1;" : "=f"(t) : "f"(u));
    return 0.5f * x * (1.0f + t);
}
__device__ __forceinline__ uint32_t pkh(__half a, __half b) {
    return (uint32_t)__half_as_ushort(a) |
           ((uint32_t)__half_as_ushort(b) << 16);
}
__device__ __forceinline__ uint32_t s2u(const void* p) {
    uint32_t a;
    asm("{ .reg .u64 t; cvta.to.shared.u64 t, %1; cvt.u32.u64 %0, t; }"
        : "=r"(a) : "l"(p));
    return a;
}

__device__ __forceinline__ void mma_f16(float* d, const uint32_t* a,
                                        const uint32_t* b) {
    asm volatile(
        "mma.sync.aligned.m16n8k16.row.col.f32.f16.f16.f32 "
        "{%0,%1,%2,%3}, {%4,%5,%6,%7}, {%8,%9}, {%0,%1,%2,%3};"
        : "+f"(d[0]), "+f"(d[1]), "+f"(d[2]), "+f"(d[3])
        : "r"(a[0]), "r"(a[1]), "r"(a[2]), "r"(a[3]),
          "r"(b[0]), "r"(b[1]));
}

#define LDSM4(r0, r1, r2, r3, addr) \
    asm volatile("ldmatrix.sync.aligned.m8n8.x4.shared.b16 {%0,%1,%2,%3}, [%4];" \
        : "=r"(r0), "=r"(r1), "=r"(r2), "=r"(r3) : "r"(addr))

#define CPASYNC16(dst, src) \
    asm volatile("cp.async.cg.shared.global [%0], [%1], 16;" \
        :: "r"(dst), "l"(src) : "memory")
#define CPCOMMIT() asm volatile("cp.async.commit_group;" ::: "memory")
#define CPWAIT2()  asm volatile("cp.async.wait_group 2;"  ::: "memory")

// chunk swizzle: 16B chunks, ci ^ bit3->bit0 (keeps ldmatrix 8-row phases conflict-free)
#define SWZ16(ci) ((uint32_t)(((ci) ^ (((ci) >> 3) & 1)) * 16))

// ---------------- embed / pool / router --------------------------------------
__global__ void gather_half_kernel(const int* __restrict__ ids,
                                   const float* __restrict__ emb)
{
    const int t = blockIdx.x;
    const int id = ids[t];
    const int c = threadIdx.x * 4;
    float4 v = *(const float4*)(emb + (size_t)id * ND + c);
    *(uint2*)(g_Xh + (size_t)t * ND + c) =
        make_uint2(pkh(__float2half_rn(v.x * ASCALE), __float2half_rn(v.y * ASCALE)),
                   pkh(__float2half_rn(v.z * ASCALE), __float2half_rn(v.w * ASCALE)));
}

__global__ void pool_partial_kernel(const int* __restrict__ ids,
                                    const float* __restrict__ emb)
{
    __shared__ int sid[128];
    const int t0 = blockIdx.x * 128;
    if (threadIdx.x < 128) sid[threadIdx.x] = ids[t0 + threadIdx.x];
    __syncthreads();
    const int c = threadIdx.x * 4;
    float4 s = make_float4(0.f, 0.f, 0.f, 0.f);
    for (int t = 0; t < 128; ++t) {
        const float4 v = *(const float4*)(emb + (size_t)sid[t] * ND + c);
        s.x += v.x; s.y += v.y; s.z += v.z; s.w += v.w;
    }
    *(float4*)(g_pool_part + blockIdx.x * ND + c) = s;
}

__global__ void pool_final_kernel()
{
    const int c = threadIdx.x * 4;
    float4 s = make_float4(0.f, 0.f, 0.f, 0.f);
    for (int b = 0; b < 64; ++b) {
        const float4 v = *(const float4*)(g_pool_part + b * ND + c);
        s.x += v.x; s.y += v.y; s.z += v.z; s.w += v.w;
    }
    const float inv = 1.0f / (float)NTOK;
    s.x *= inv; s.y *= inv; s.z *= inv; s.w *= inv;
    *(float4*)(g_pool + c) = s;
}

__global__ void router_kernel(const float* __restrict__ w_router)
{
    __shared__ float slog[NEXP];
    const int warp = threadIdx.x >> 5;
    const int lane = threadIdx.x & 31;
    float s = 0.f;
    for (int d = lane; d < ND; d += 32)
        s += g_pool[d] * w_router[d * NEXP + warp];
    #pragma unroll
    for (int o = 16; o > 0; o >>= 1) s += __shfl_down_sync(0xffffffffu, s, o);
    if (lane == 0) slog[warp] = s;
    __syncthreads();
    if (threadIdx.x == 0) {
        float v0 = -1e30f, v1 = -1e30f; int i0 = 0, i1 = 0;
        for (int n = 0; n < NEXP; ++n) {
            const float l = slog[n];
            if (l > v0) { v1 = v0; i1 = i0; v0 = l; i0 = n; }
            else if (l > v1) { v1 = l; i1 = n; }
        }
        const float e1  = expf(v1 - v0);
        const float den = 1.0f + e1;
        g_eidx[0] = i0; g_eidx[1] = i1;
        g_ewt[0] = 1.0f / den; g_ewt[1] = e1 / den;
    }
}

// ---------------- weight transpose (fp16 single) -------------------------------
__global__ void transpose_half_kernel(const float* __restrict__ src,
                                      int K, int N, long src_z, int mode)
{
    __shared__ float tile[32][33];
    const int e = blockIdx.z;
    __half* dh; long dst_z; int ld; int use_e;
    if (mode == 0)      { dh = g_w1f; dst_z = (long)NH * ND; ld = ND;   use_e = 1; }
    else if (mode == 1) { dh = g_w2f; dst_z = NH;            ld = KCAT; use_e = 1; }
    else                { dh = g_whf; dst_z = 0;             ld = ND;   use_e = 0; }

    const int sel = use_e ? g_eidx[e] : e;
    const float* in = src + (size_t)sel * src_z;
    dh += (size_t)e * dst_z;

    const int n0 = blockIdx.x * 32, k0 = blockIdx.y * 32;
    const int tx = threadIdx.x, ty = threadIdx.y;   // (32, 8)
    #pragma unroll
    for (int j = 0; j < 32; j += 8)
        tile[ty + j][tx] = in[(size_t)(k0 + ty + j) * N + n0 + tx];
    __syncthreads();
    #pragma unroll
    for (int j = 0; j < 32; j += 8)
        dh[(size_t)(n0 + ty + j) * ld + k0 + tx] =
            __float2half_rn(tile[tx][ty + j]);
}

// ---------------- fp16 single-product mma GEMM ---------------------------------
// C = A @ B^T, both operands single fp16 (A carries x1024 scale).
// 128-thread CTA, 4 warps 2x2, warp tile 64x64, 4-stage cp.async, 2 CTAs/SM.
// (exact round-12 structure — the 2291us baseline)
#define BM 128
#define BN 128
#define BK 16
#define NSTAGE 4
#define OFF_BH 4096
#define STAGE  8192
#define SMEM_BYTES (NSTAGE * STAGE)   // 32768 per CTA; 2 CTAs = 64KB/SM

// MODE 0: H = gelu(X @ w1t[e]^T)*wt[e] -> Hh   (grid.z = expert)
// MODE 1: O = H @ w2t^T -> Oh
// MODE 2: LOGITS = O @ wht^T -> fp32 out
template<int MODE>
__global__ void __launch_bounds__(128, 2)
mma_gemm_kernel(float* __restrict__ Cext)
{
    constexpr int K   = (MODE == 1) ? KCAT : ND;
    constexpr int NT  = K / BK;
    constexpr int LDC = (MODE == 0) ? KCAT : ((MODE == 1) ? ND : NV);

    const __half *Ah, *Bh_;
    if (MODE == 0)      { Ah = g_Xh; Bh_ = g_w1f; }
    else if (MODE == 1) { Ah = g_Hh; Bh_ = g_w2f; }
    else                { Ah = g_Oh; Bh_ = g_whf; }

    extern __shared__ __align__(16) uint8_t smraw[];
    const uint32_t smb = s2u(smraw);

    const int tid  = threadIdx.x;
    const int w    = tid >> 5, lane = tid & 31;
    const int g    = lane >> 2, tig = lane & 3;
    const int mb   = (w >> 1) * 64;        // 2 m-warps
    const int nb   = (w & 1) * 64;         // 2 n-warps
    const int bm   = blockIdx.y * BM;
    const int bn   = blockIdx.x * BN;

    float wt = 1.f; int ccol0 = bn;
    if (MODE == 0) {
        const int e = blockIdx.z;
        wt    = g_ewt[e];
        Bh_  += (size_t)e * NH * ND;
        ccol0 = e * NH + bn;
    }

    const __half* Ab_h = Ah + (size_t)bm * K;
    const __half* Bb_h = Bh_ + (size_t)bn * K;

    // fill: 512 16B chunks / 128 threads = 4 each (2 per region)
    auto fill = [&](uint32_t sbase, int k0) {
        #pragma unroll
        for (int i = 0; i < 2; ++i) {
            const int ci = i * 128 + tid;
            const size_t go = (size_t)(ci >> 1) * K + k0 + (ci & 1) * 8;
            CPASYNC16(sbase + SWZ16(ci),          Ab_h + go);
            CPASYNC16(sbase + OFF_BH + SWZ16(ci), Bb_h + go);
        }
    };

    // ldmatrix lane offsets (verified mapping, rounds 5-12)
    const int am = lane >> 3;
    const int a_ci0 = (mb + ((am & 1) << 3) + (lane & 7)) * 2 + (am >> 1);
    const uint32_t aoff = SWZ16(a_ci0);
    const int bmm = lane >> 3;
    const int b_ci0 = (nb + ((bmm >> 1) << 3) + (lane & 7)) * 2 + (bmm & 1);
    const uint32_t boff = SWZ16(b_ci0);

    float acc[4][8][4];
    #pragma unroll
    for (int i = 0; i < 4; ++i)
        #pragma unroll
        for (int j = 0; j < 8; ++j)
            #pragma unroll
            for (int q = 0; q < 4; ++q) acc[i][j][q] = 0.f;

    // prologue: stages 0,1,2 in flight
    fill(smb, 0);                  CPCOMMIT();
    fill(smb + STAGE, BK);         CPCOMMIT();
    fill(smb + 2 * STAGE, 2 * BK); CPCOMMIT();

    int rd = 0, wr = 3;
    #pragma unroll 1
    for (int t = 0; t < NT; ++t) {
        CPWAIT2();
        __syncthreads();

        const uint32_t sb = smb + rd * STAGE;

        // B fragments for all 8 n-tiles
        uint32_t Bhf[8][2];
        #pragma unroll
        for (int p = 0; p < 4; ++p) {
            uint32_t r0, r1, r2, r3;
            LDSM4(r0, r1, r2, r3, sb + OFF_BH + boff + p * 512);
            Bhf[2*p][0] = r0; Bhf[2*p][1] = r1;
            Bhf[2*p+1][0] = r2; Bhf[2*p+1][1] = r3;
        }

        if (t + 3 < NT) fill(smb + wr * STAGE, (t + 3) * BK);
        CPCOMMIT();

        #pragma unroll
        for (int mt = 0; mt < 4; ++mt) {
            uint32_t Ahf[4];
            LDSM4(Ahf[0], Ahf[1], Ahf[2], Ahf[3], sb + aoff + mt * 512);
            #pragma unroll
            for (int nt = 0; nt < 8; ++nt)
                mma_f16(acc[mt][nt], Ahf, Bhf[nt]);
        }

        rd = (rd + 1) & 3;
        wr = (wr + 1) & 3;
    }

    // ---- epilogue (acc carries x1024 scale from A) ----
    #pragma unroll
    for (int mt = 0; mt < 4; ++mt) {
        const int row0 = bm + mb + mt * 16 + g;
        #pragma unroll
        for (int rr = 0; rr < 2; ++rr) {
            const int row = row0 + rr * 8;
            const size_t base = (size_t)row * LDC + ccol0 + nb + 2 * tig;
            #pragma unroll
            for (int nt = 0; nt < 8; ++nt) {
                float v0 = acc[mt][nt][2 * rr];
                float v1 = acc[mt][nt][2 * rr + 1];
                if (MODE == 0) {   // true value, fast gelu, re-apply scale
                    v0 = gelu_fast(v0 * INVS) * wt * ASCALE;
                    v1 = gelu_fast(v1 * INVS) * wt * ASCALE;
                }
                if (MODE == 2) {
                    *(float2*)(Cext + base + nt * 8) =
                        make_float2(v0 * INVS, v1 * INVS);
                } else {
                    __half* dh = (MODE == 0) ? g_Hh : g_Oh;
                    *(uint32_t*)(dh + base + nt * 8) =
                        pkh(__float2half_rn(v0), __float2half_rn(v1));
                }
            }
        }
    }
}

// ---------------- entry point -------------------------------------------------
extern "C" void kernel_launch(void* const* d_in, const int* in_sizes, int n_in,
                              void* d_out, int out_size)
{
    (void)in_sizes; (void)n_in; (void)out_size;
    const int*   ids = (const int*)  d_in[0];
    const float* emb = (const float*)d_in[1];
    const float* wr  = (const float*)d_in[2];
    const float* w1  = (const float*)d_in[3];
    const float* w2  = (const float*)d_in[4];
    const float* wh  = (const float*)d_in[5];
    float* out = (float*)d_out;

    cudaFuncSetAttribute(mma_gemm_kernel<0>, cudaFuncAttributeMaxDynamicSharedMemorySize, SMEM_BYTES);
    cudaFuncSetAttribute(mma_gemm_kernel<1>, cudaFuncAttributeMaxDynamicSharedMemorySize, SMEM_BYTES);
    cudaFuncSetAttribute(mma_gemm_kernel<2>, cudaFuncAttributeMaxDynamicSharedMemorySize, SMEM_BYTES);

    gather_half_kernel <<<NTOK, 256>>>(ids, emb);
    pool_partial_kernel<<<64,   256>>>(ids, emb);
    pool_final_kernel  <<<1,    256>>>();
    router_kernel      <<<1,    512>>>(wr);

    transpose_half_kernel<<<dim3(NH / 32, ND / 32, 2), dim3(32, 8)>>>(w1, ND, NH, (long)ND * NH, 0);
    transpose_half_kernel<<<dim3(ND / 32, NH / 32, 2), dim3(32, 8)>>>(w2, NH, ND, (long)NH * ND, 1);
    transpose_half_kernel<<<dim3(NV / 32, ND / 32, 1), dim3(32, 8)>>>(wh, ND, NV, 0, 2);

    mma_gemm_kernel<0><<<dim3(NH / BN, NTOK / BM, 2), 128, SMEM_BYTES>>>(nullptr);
    mma_gemm_kernel<1><<<dim3(ND / BN, NTOK / BM, 1), 128, SMEM_BYTES>>>(nullptr);
    mma_gemm_kernel<2><<<dim3(NV / BN, NTOK / BM, 1), 128, SMEM_BYTES>>>(out);
}